// round 3
// baseline (speedup 1.0000x reference)
#include <cuda_runtime.h>
#include <math.h>

// ---------------- problem constants ----------------
#define D_IN   120000
#define BATCH  512
#define H1     600
#define H2     300
#define H3     200

// ---------------- L1 CSC-spmm config ----------------
#define RB      96            // rows per bucket (96*128*4 = 49152 B static smem)
#define NBUCK   7             // ceil(600/96)
#define BT      128           // batch lanes per block
#define BTILES  4             // 512 / 128
#define C1      21            // 21*7*4 = 588 blocks ~ 1 wave @ 4 blocks/SM
#define DC      5715          // ceil(120000/21)
#define NB1     (NBUCK * D_IN)          // 840000 histogram bins
#define SCAN_B  1024
#define NSCAN_BLK ((NB1 + SCAN_B - 1) / SCAN_B)   // 821

#define MAX_NNZ1 7200000
#define MAX_NNZS 36000

// ---------------- device scratch (static: no runtime allocation) ----------------
__device__ float  g_xT[(size_t)D_IN * BATCH];        // 245.8 MB transposed input
__device__ float2 g_ent1[MAX_NNZ1];                  // bucketed (r_local, v) for L1
__device__ int    g_ptr1[NB1 + 1];
__device__ int    g_cur1[NB1];                       // histogram, then scatter cursor
__device__ int    g_bsum[1024];
__device__ int    g_bsumex[1024];
__device__ float  g_part1[(size_t)C1 * H1 * BATCH];  // 25.8 MB partial sums
__device__ float  g_bufA[H1 * BATCH];
__device__ float  g_bufB[H1 * BATCH];
__device__ float2 g_entS[MAX_NNZS];
__device__ int    g_ptrS[H1 + 1];
__device__ int    g_curS[H1];

// ---------------- transpose x (B x D) -> xT (D x B) ----------------
__global__ void k_transpose(const float* __restrict__ x) {
    __shared__ float tile[32][33];
    int d0 = blockIdx.x * 32;
    int b0 = blockIdx.y * 32;
    int tx = threadIdx.x, ty = threadIdx.y;      // block (32, 8)
#pragma unroll
    for (int j = 0; j < 32; j += 8)
        tile[ty + j][tx] = x[(size_t)(b0 + ty + j) * D_IN + d0 + tx];
    __syncthreads();
#pragma unroll
    for (int j = 0; j < 32; j += 8)
        g_xT[(size_t)(d0 + ty + j) * BATCH + b0 + tx] = tile[tx][ty + j];
}

// ---------------- zero kernels (globals referenced in-kernel, not passed) ----------------
__global__ void k_zero1() {
    int i = blockIdx.x * blockDim.x + threadIdx.x;
    if (i < NB1) g_cur1[i] = 0;
}
__global__ void k_zeroS(int n) {
    int i = blockIdx.x * blockDim.x + threadIdx.x;
    if (i < n) g_curS[i] = 0;
}

// ---------------- L1 build: histogram / 3-phase scan / scatter ----------------
__global__ void k_hist1(const int* __restrict__ idx, int nnz) {
    int e = blockIdx.x * blockDim.x + threadIdx.x;
    if (e < nnz) {
        int r = idx[e];
        int c = idx[nnz + e];
        atomicAdd(&g_cur1[(r / RB) * D_IN + c], 1);
    }
}

__global__ void k_scan1() {  // per-block reduction of counts
    __shared__ int s[SCAN_B];
    int i = blockIdx.x * SCAN_B + threadIdx.x;
    int v = (i < NB1) ? g_cur1[i] : 0;
    s[threadIdx.x] = v;
    __syncthreads();
    for (int o = SCAN_B / 2; o > 0; o >>= 1) {
        if (threadIdx.x < o) s[threadIdx.x] += s[threadIdx.x + o];
        __syncthreads();
    }
    if (threadIdx.x == 0) g_bsum[blockIdx.x] = s[0];
}

__global__ void k_scan2() {  // single block: exclusive scan of block sums
    __shared__ int s[1024];
    int t = threadIdx.x;
    int v = (t < NSCAN_BLK) ? g_bsum[t] : 0;
    s[t] = v;
    __syncthreads();
    for (int o = 1; o < 1024; o <<= 1) {
        int a = (t >= o) ? s[t - o] : 0;
        __syncthreads();
        s[t] += a;
        __syncthreads();
    }
    if (t < NSCAN_BLK) g_bsumex[t] = s[t] - v;
}

__global__ void k_scan3() {  // final exclusive scan, write ptr + cursor
    __shared__ int s[SCAN_B];
    int i = blockIdx.x * SCAN_B + threadIdx.x;
    int v = (i < NB1) ? g_cur1[i] : 0;
    s[threadIdx.x] = v;
    __syncthreads();
    for (int o = 1; o < SCAN_B; o <<= 1) {
        int a = (threadIdx.x >= o) ? s[threadIdx.x - o] : 0;
        __syncthreads();
        s[threadIdx.x] += a;
        __syncthreads();
    }
    int incl = s[threadIdx.x];
    int base = g_bsumex[blockIdx.x];
    if (i < NB1) {
        int p = base + incl - v;
        g_ptr1[i] = p;
        g_cur1[i] = p;
        if (i == NB1 - 1) g_ptr1[NB1] = base + incl;
    }
}

__global__ void k_scatter1(const int* __restrict__ idx, const float* __restrict__ val, int nnz) {
    int e = blockIdx.x * blockDim.x + threadIdx.x;
    if (e < nnz) {
        int r = idx[e];
        int c = idx[nnz + e];
        int bk = r / RB;
        int pos = atomicAdd(&g_cur1[bk * D_IN + c], 1);
        g_ent1[pos] = make_float2(__int_as_float(r - bk * RB), val[e]);
    }
}

// ---------------- L1 SpMM: stream x once, scatter into smem accumulators ----------------
// Race-free: every thread only touches acc indices with (i % BT == tid):
// no atomics, no barriers in the hot loop.
__global__ __launch_bounds__(BT) void k_spmm1() {
    __shared__ float acc[RB * BT];   // 49152 B -> 4 blocks/SM
    int chunk  = blockIdx.x;
    int bucket = blockIdx.y;
    int bt     = blockIdx.z;
    int tid    = threadIdx.x;

    float* accp = acc + tid;
#pragma unroll
    for (int i = 0; i < RB; i++) accp[i * BT] = 0.f;

    int c0 = chunk * DC;
    int c1 = min(c0 + DC, D_IN);
    int xoff = bt * BT + tid;
    const int* __restrict__ ptr = g_ptr1 + bucket * D_IN;
    const float* __restrict__ xp = g_xT + xoff;

    for (int c = c0; c < c1; c++) {
        int beg = ptr[c];
        int end = ptr[c + 1];
        if (beg == end) continue;
        float xv = xp[(size_t)c * BATCH];
#pragma unroll 4
        for (int e = beg; e < end; e++) {
            float2 E = g_ent1[e];
            int rl = __float_as_int(E.x);
            accp[rl * BT] += E.y * xv;
        }
    }

    // non-atomic partial writes; reduced in k_reduce1
#pragma unroll 4
    for (int i = 0; i < RB; i++) {
        int rg = bucket * RB + i;
        if (rg < H1)
            g_part1[(size_t)(chunk * H1 + rg) * BATCH + xoff] = accp[i * BT];
    }
}

__global__ void k_reduce1(const float* __restrict__ bias) {
    int r = blockIdx.x;
    int o = blockIdx.y * BT + threadIdx.x;
    float s = bias[r];
#pragma unroll
    for (int k = 0; k < C1; k++)
        s += g_part1[(size_t)(k * H1 + r) * BATCH + o];
    g_bufA[r * BATCH + o] = s;
}

// ---------------- BatchNorm (training mode, biased var) + SiLU ----------------
// A2B=true: g_bufA -> g_bufB, else g_bufB -> g_bufA
template <bool A2B>
__global__ void k_bn_silu(const float* __restrict__ g, const float* __restrict__ be) {
    const float* __restrict__ in = A2B ? g_bufA : g_bufB;
    float* __restrict__ out      = A2B ? g_bufB : g_bufA;
    __shared__ float sS[8], sQ[8];
    int r = blockIdx.x, tid = threadIdx.x;   // 256 threads
    float v0 = in[r * BATCH + tid];
    float v1 = in[r * BATCH + 256 + tid];
    float s = v0 + v1;
    float q = v0 * v0 + v1 * v1;
#pragma unroll
    for (int o = 16; o > 0; o >>= 1) {
        s += __shfl_down_sync(0xffffffffu, s, o);
        q += __shfl_down_sync(0xffffffffu, q, o);
    }
    if ((tid & 31) == 0) { sS[tid >> 5] = s; sQ[tid >> 5] = q; }
    __syncthreads();
    if (tid < 8) {
        s = sS[tid]; q = sQ[tid];
#pragma unroll
        for (int o = 4; o > 0; o >>= 1) {
            s += __shfl_down_sync(0xffu, s, o);
            q += __shfl_down_sync(0xffu, q, o);
        }
        if (tid == 0) { sS[0] = s; sQ[0] = q; }
    }
    __syncthreads();
    float mean = sS[0] * (1.f / BATCH);
    float var  = sQ[0] * (1.f / BATCH) - mean * mean;
    float sc = rsqrtf(var + 1e-5f) * g[r];
    float sh = be[r];
    float z0 = (v0 - mean) * sc + sh;
    float z1 = (v1 - mean) * sc + sh;
    out[r * BATCH + tid]       = z0 / (1.f + expf(-z0));
    out[r * BATCH + 256 + tid] = z1 / (1.f + expf(-z1));
}

// ---------------- small-layer CSR build ----------------
__global__ void k_histS(const int* __restrict__ idx, int nnz) {
    int e = blockIdx.x * blockDim.x + threadIdx.x;
    if (e < nnz) atomicAdd(&g_curS[idx[e]], 1);
}

__global__ void k_scanS(int n) {   // single block, n <= 1024
    __shared__ int s[1024];
    int t = threadIdx.x;
    int v = (t < n) ? g_curS[t] : 0;
    s[t] = v;
    __syncthreads();
    for (int o = 1; o < 1024; o <<= 1) {
        int a = (t >= o) ? s[t - o] : 0;
        __syncthreads();
        s[t] += a;
        __syncthreads();
    }
    if (t < n) { int p = s[t] - v; g_ptrS[t] = p; g_curS[t] = p; }
    if (t == 1023) g_ptrS[n] = s[1023];
}

__global__ void k_scatterS(const int* __restrict__ idx, const float* __restrict__ val, int nnz) {
    int e = blockIdx.x * blockDim.x + threadIdx.x;
    if (e < nnz) {
        int r = idx[e];
        int c = idx[nnz + e];
        int pos = atomicAdd(&g_curS[r], 1);
        g_entS[pos] = make_float2(__int_as_float(c), val[e]);
    }
}

// ---------------- small-layer SpMM (register accumulator per lane) ----------------
// MODE 0: raw y -> other buffer   MODE 1: fused SiLU -> other buffer
// MODE 2: final, transposed (B, H3) write to `outp`
// IN_A=true reads g_bufA (writes g_bufB for MODE 0/1), else the reverse.
template <int MODE, bool IN_A>
__global__ __launch_bounds__(BT) void k_spmmS(const float* __restrict__ bias,
                                              float* __restrict__ outp) {
    const float* __restrict__ in = IN_A ? g_bufA : g_bufB;
    float* __restrict__ outbuf   = IN_A ? g_bufB : g_bufA;
    int r = blockIdx.x;
    int o = blockIdx.y * BT + threadIdx.x;
    float acc = bias[r];
    int beg = g_ptrS[r];
    int end = g_ptrS[r + 1];
#pragma unroll 4
    for (int e = beg; e < end; e++) {
        float2 E = g_entS[e];
        int c = __float_as_int(E.x);
        acc += E.y * in[c * BATCH + o];
    }
    if (MODE == 0)      outbuf[r * BATCH + o] = acc;
    else if (MODE == 1) outbuf[r * BATCH + o] = acc / (1.f + expf(-acc));
    else                outp[o * H3 + r] = acc;
}

// ---------------- host orchestration ----------------
static inline int cdiv(int a, int b) { return (a + b - 1) / b; }

static void build_small(const int* idx, const float* val, int nnz, int out_d) {
    k_zeroS<<<cdiv(out_d, 256), 256>>>(out_d);
    k_histS<<<cdiv(nnz, 256), 256>>>(idx, nnz);
    k_scanS<<<1, 1024>>>(out_d);
    k_scatterS<<<cdiv(nnz, 256), 256>>>(idx, val, nnz);
}

extern "C" void kernel_launch(void* const* d_in, const int* in_sizes, int n_in,
                              void* d_out, int out_size) {
    (void)n_in; (void)out_size;
    const float* x    = (const float*)d_in[0];
    const int*   idx1 = (const int*)d_in[1];
    const float* val1 = (const float*)d_in[2];
    const float* b1   = (const float*)d_in[3];
    const int*   idx2 = (const int*)d_in[4];
    const float* val2 = (const float*)d_in[5];
    const float* b2   = (const float*)d_in[6];
    const int*   idx3 = (const int*)d_in[7];
    const float* val3 = (const float*)d_in[8];
    const float* b3   = (const float*)d_in[9];
    const int*   idx4 = (const int*)d_in[10];
    const float* val4 = (const float*)d_in[11];
    const float* b4   = (const float*)d_in[12];
    const int*   idx5 = (const int*)d_in[13];
    const float* val5 = (const float*)d_in[14];
    const float* b5   = (const float*)d_in[15];
    const float* g1   = (const float*)d_in[16];
    const float* be1  = (const float*)d_in[17];
    const float* g2   = (const float*)d_in[18];
    const float* be2  = (const float*)d_in[19];
    const float* g3   = (const float*)d_in[20];
    const float* be3  = (const float*)d_in[21];
    float* outp = (float*)d_out;

    int nnz1 = in_sizes[2];
    int nnz2 = in_sizes[5];
    int nnz3 = in_sizes[8];
    int nnz4 = in_sizes[11];
    int nnz5 = in_sizes[14];

    // x -> xT
    k_transpose<<<dim3(D_IN / 32, BATCH / 32), dim3(32, 8)>>>(x);

    // ---- layer 1: CSC build ----
    k_zero1<<<cdiv(NB1, 256), 256>>>();
    k_hist1<<<cdiv(nnz1, 256), 256>>>(idx1, nnz1);
    k_scan1<<<NSCAN_BLK, SCAN_B>>>();
    k_scan2<<<1, 1024>>>();
    k_scan3<<<NSCAN_BLK, SCAN_B>>>();
    k_scatter1<<<cdiv(nnz1, 256), 256>>>(idx1, val1, nnz1);

    // ---- layer 1: SpMM + reduce + BN/SiLU ----
    k_spmm1<<<dim3(C1, NBUCK, BTILES), BT>>>();
    k_reduce1<<<dim3(H1, BTILES), BT>>>(b1);           // -> bufA = y1
    k_bn_silu<true><<<H1, 256>>>(g1, be1);             // bufA -> bufB = h1

    // ---- layer 2 (600 -> 600, SiLU fused, no BN) ----
    build_small(idx2, val2, nnz2, H1);
    k_spmmS<1, false><<<dim3(H1, BTILES), BT>>>(b2, nullptr);   // bufB -> bufA = h2

    // ---- layer 3 (600 -> 300) + BN/SiLU ----
    build_small(idx3, val3, nnz3, H2);
    k_spmmS<0, true><<<dim3(H2, BTILES), BT>>>(b3, nullptr);    // bufA -> bufB = y3
    k_bn_silu<false><<<H2, 256>>>(g2, be2);                     // bufB -> bufA = h3

    // ---- layer 4 (300 -> 200) + BN/SiLU ----
    build_small(idx4, val4, nnz4, H3);
    k_spmmS<0, true><<<dim3(H3, BTILES), BT>>>(b4, nullptr);    // bufA -> bufB = y4
    k_bn_silu<false><<<H3, 256>>>(g3, be3);                     // bufB -> bufA = h4

    // ---- layer 5 (200 -> 200, final, transposed (B, H3) output) ----
    build_small(idx5, val5, nnz5, H3);
    k_spmmS<2, true><<<dim3(H3, BTILES), BT>>>(b5, outp);
}

// round 4
// speedup vs baseline: 1.0852x; 1.0852x over previous
#include <cuda_runtime.h>
#include <math.h>

// ---------------- problem constants ----------------
#define D_IN   120000
#define BATCH  512
#define H1     600
#define H2     300
#define H3     200

// ---------------- L1 CSC-spmm config ----------------
#define RB      96            // rows per bucket (96*128*4 = 49152 B static smem)
#define NBUCK   7             // ceil(600/96)
#define BT      128           // batch lanes per block
#define BTILES  4             // 512 / 128
#define C1      20            // chunks: 20*6000 = 120000 exactly
#define DC      6000          // divisible by PF
#define PF      8             // column prefetch-pipeline depth
#define NB1     (NBUCK * D_IN)          // 840000 histogram bins
#define SCAN_B  1024
#define NSCAN_BLK ((NB1 + SCAN_B - 1) / SCAN_B)   // 821

#define MAX_NNZ1 7200000
#define MAX_NNZS 36000

// ---------------- device scratch (static: no runtime allocation) ----------------
__device__ float  g_xT[(size_t)D_IN * BATCH];        // 245.8 MB transposed input
__device__ float2 g_ent1[MAX_NNZ1];                  // (row_byte_off, val) per entry
__device__ int    g_ptr1[NB1 + 1];
__device__ int    g_cur1[NB1];                       // histogram, then scatter cursor
__device__ int    g_bsum[1024];
__device__ int    g_bsumex[1024];
__device__ float  g_part1[(size_t)C1 * H1 * BATCH];  // 24.6 MB partial sums
__device__ float  g_bufA[H1 * BATCH];
__device__ float  g_bufB[H1 * BATCH];
__device__ float2 g_entS[MAX_NNZS];
__device__ int    g_ptrS[H1 + 1];
__device__ int    g_curS[H1];

// ---------------- transpose x (B x D) -> xT (D x B) ----------------
__global__ void k_transpose(const float* __restrict__ x) {
    __shared__ float tile[32][33];
    int d0 = blockIdx.x * 32;
    int b0 = blockIdx.y * 32;
    int tx = threadIdx.x, ty = threadIdx.y;      // block (32, 8)
#pragma unroll
    for (int j = 0; j < 32; j += 8)
        tile[ty + j][tx] = x[(size_t)(b0 + ty + j) * D_IN + d0 + tx];
    __syncthreads();
#pragma unroll
    for (int j = 0; j < 32; j += 8)
        g_xT[(size_t)(d0 + ty + j) * BATCH + b0 + tx] = tile[tx][ty + j];
}

// ---------------- zero kernels ----------------
__global__ void k_zero1() {
    int i = blockIdx.x * blockDim.x + threadIdx.x;
    if (i < NB1) g_cur1[i] = 0;
}
__global__ void k_zeroS(int n) {
    int i = blockIdx.x * blockDim.x + threadIdx.x;
    if (i < n) g_curS[i] = 0;
}

// ---------------- L1 build: histogram / 3-phase scan / scatter ----------------
__global__ void k_hist1(const int* __restrict__ idx, int nnz) {
    int e = blockIdx.x * blockDim.x + threadIdx.x;
    if (e < nnz) {
        int r = idx[e];
        int c = idx[nnz + e];
        atomicAdd(&g_cur1[(r / RB) * D_IN + c], 1);
    }
}

__global__ void k_scan1() {  // per-block reduction of counts
    __shared__ int s[SCAN_B];
    int i = blockIdx.x * SCAN_B + threadIdx.x;
    int v = (i < NB1) ? g_cur1[i] : 0;
    s[threadIdx.x] = v;
    __syncthreads();
    for (int o = SCAN_B / 2; o > 0; o >>= 1) {
        if (threadIdx.x < o) s[threadIdx.x] += s[threadIdx.x + o];
        __syncthreads();
    }
    if (threadIdx.x == 0) g_bsum[blockIdx.x] = s[0];
}

__global__ void k_scan2() {  // single block: exclusive scan of block sums
    __shared__ int s[1024];
    int t = threadIdx.x;
    int v = (t < NSCAN_BLK) ? g_bsum[t] : 0;
    s[t] = v;
    __syncthreads();
    for (int o = 1; o < 1024; o <<= 1) {
        int a = (t >= o) ? s[t - o] : 0;
        __syncthreads();
        s[t] += a;
        __syncthreads();
    }
    if (t < NSCAN_BLK) g_bsumex[t] = s[t] - v;
}

__global__ void k_scan3() {  // final exclusive scan, write ptr + cursor
    __shared__ int s[SCAN_B];
    int i = blockIdx.x * SCAN_B + threadIdx.x;
    int v = (i < NB1) ? g_cur1[i] : 0;
    s[threadIdx.x] = v;
    __syncthreads();
    for (int o = 1; o < SCAN_B; o <<= 1) {
        int a = (threadIdx.x >= o) ? s[threadIdx.x - o] : 0;
        __syncthreads();
        s[threadIdx.x] += a;
        __syncthreads();
    }
    int incl = s[threadIdx.x];
    int base = g_bsumex[blockIdx.x];
    if (i < NB1) {
        int p = base + incl - v;
        g_ptr1[i] = p;
        g_cur1[i] = p;
        if (i == NB1 - 1) g_ptr1[NB1] = base + incl;
    }
}

__global__ void k_scatter1(const int* __restrict__ idx, const float* __restrict__ val, int nnz) {
    int e = blockIdx.x * blockDim.x + threadIdx.x;
    if (e < nnz) {
        int r = idx[e];
        int c = idx[nnz + e];
        int bk = r / RB;
        int pos = atomicAdd(&g_cur1[bk * D_IN + c], 1);
        // store premultiplied byte offset: r_local * BT * 4  (max 95*512 < 2^24, exact in fp-bits trick)
        g_ent1[pos] = make_float2(__int_as_float((r - bk * RB) * (BT * 4)), val[e]);
    }
}

// ---------------- L1 SpMM: software-pipelined column stream ----------------
// Race-free: every thread only touches its own smem lane; no atomics/barriers in hot loop.
// Columns processed in groups of PF; next group's x values + ptr ends are
// prefetched (MLP=PF) while the current group is processed.
__global__ __launch_bounds__(BT) void k_spmm1() {
    __shared__ float acc[RB * BT];   // 49152 B -> 4 blocks/SM
    int bucket = blockIdx.x;
    int bt     = blockIdx.y;
    int chunk  = blockIdx.z;
    int tid    = threadIdx.x;

    // byte-addressed accumulator base for this thread's lane
    char* accb = (char*)acc + tid * 4;
#pragma unroll
    for (int i = 0; i < RB; i++) *(float*)(accb + i * (BT * 4)) = 0.f;

    int c0 = chunk * DC;
    int c1 = c0 + DC;                       // exact: C1*DC == D_IN
    int xoff = bt * BT + tid;
    const int* __restrict__ ptr = g_ptr1 + bucket * D_IN;
    const float* __restrict__ xp = g_xT + xoff;
    const float2* __restrict__ ent = g_ent1;

    float xc[PF]; int pc[PF];
#pragma unroll
    for (int i = 0; i < PF; i++) xc[i] = xp[(size_t)(c0 + i) * BATCH];
#pragma unroll
    for (int i = 0; i < PF; i++) pc[i] = ptr[c0 + i + 1];
    int beg = ptr[c0];

    for (int cb = c0; cb < c1; cb += PF) {
        // prefetch next group (clamped indices keep loads in-bounds; values unused on last iter)
        float xn[PF]; int pn[PF];
        int nb = cb + PF;
#pragma unroll
        for (int i = 0; i < PF; i++) {
            int c = nb + i; c = (c < D_IN) ? c : (D_IN - 1);
            xn[i] = xp[(size_t)c * BATCH];
        }
#pragma unroll
        for (int i = 0; i < PF; i++) {
            int c = nb + i + 1; c = (c < D_IN) ? c : D_IN;
            pn[i] = ptr[c];
        }

        // process current group
#pragma unroll
        for (int i = 0; i < PF; i++) {
            int end = pc[i];
            float xv = xc[i];
#pragma unroll 4
            for (int e = beg; e < end; e++) {
                float2 E = ent[e];
                int off = __float_as_int(E.x);
                float* a = (float*)(accb + off);
                *a += E.y * xv;
            }
            beg = end;
        }

#pragma unroll
        for (int i = 0; i < PF; i++) { xc[i] = xn[i]; pc[i] = pn[i]; }
    }

    // non-atomic partial writes; reduced in k_reduce1
#pragma unroll 4
    for (int i = 0; i < RB; i++) {
        int rg = bucket * RB + i;
        if (rg < H1)
            g_part1[(size_t)(chunk * H1 + rg) * BATCH + xoff] = *(float*)(accb + i * (BT * 4));
    }
}

__global__ void k_reduce1(const float* __restrict__ bias) {
    int r = blockIdx.x;
    int o = blockIdx.y * BT + threadIdx.x;
    float s = bias[r];
#pragma unroll
    for (int k = 0; k < C1; k++)
        s += g_part1[(size_t)(k * H1 + r) * BATCH + o];
    g_bufA[r * BATCH + o] = s;
}

// ---------------- BatchNorm (training mode, biased var) + SiLU ----------------
template <bool A2B>
__global__ void k_bn_silu(const float* __restrict__ g, const float* __restrict__ be) {
    const float* __restrict__ in = A2B ? g_bufA : g_bufB;
    float* __restrict__ out      = A2B ? g_bufB : g_bufA;
    __shared__ float sS[8], sQ[8];
    int r = blockIdx.x, tid = threadIdx.x;   // 256 threads
    float v0 = in[r * BATCH + tid];
    float v1 = in[r * BATCH + 256 + tid];
    float s = v0 + v1;
    float q = v0 * v0 + v1 * v1;
#pragma unroll
    for (int o = 16; o > 0; o >>= 1) {
        s += __shfl_down_sync(0xffffffffu, s, o);
        q += __shfl_down_sync(0xffffffffu, q, o);
    }
    if ((tid & 31) == 0) { sS[tid >> 5] = s; sQ[tid >> 5] = q; }
    __syncthreads();
    if (tid < 8) {
        s = sS[tid]; q = sQ[tid];
#pragma unroll
        for (int o = 4; o > 0; o >>= 1) {
            s += __shfl_down_sync(0xffu, s, o);
            q += __shfl_down_sync(0xffu, q, o);
        }
        if (tid == 0) { sS[0] = s; sQ[0] = q; }
    }
    __syncthreads();
    float mean = sS[0] * (1.f / BATCH);
    float var  = sQ[0] * (1.f / BATCH) - mean * mean;
    float sc = rsqrtf(var + 1e-5f) * g[r];
    float sh = be[r];
    float z0 = (v0 - mean) * sc + sh;
    float z1 = (v1 - mean) * sc + sh;
    out[r * BATCH + tid]       = z0 / (1.f + expf(-z0));
    out[r * BATCH + 256 + tid] = z1 / (1.f + expf(-z1));
}

// ---------------- small-layer CSR build ----------------
__global__ void k_histS(const int* __restrict__ idx, int nnz) {
    int e = blockIdx.x * blockDim.x + threadIdx.x;
    if (e < nnz) atomicAdd(&g_curS[idx[e]], 1);
}

__global__ void k_scanS(int n) {   // single block, n <= 1024
    __shared__ int s[1024];
    int t = threadIdx.x;
    int v = (t < n) ? g_curS[t] : 0;
    s[t] = v;
    __syncthreads();
    for (int o = 1; o < 1024; o <<= 1) {
        int a = (t >= o) ? s[t - o] : 0;
        __syncthreads();
        s[t] += a;
        __syncthreads();
    }
    if (t < n) { int p = s[t] - v; g_ptrS[t] = p; g_curS[t] = p; }
    if (t == 1023) g_ptrS[n] = s[1023];
}

__global__ void k_scatterS(const int* __restrict__ idx, const float* __restrict__ val, int nnz) {
    int e = blockIdx.x * blockDim.x + threadIdx.x;
    if (e < nnz) {
        int r = idx[e];
        int c = idx[nnz + e];
        int pos = atomicAdd(&g_curS[r], 1);
        g_entS[pos] = make_float2(__int_as_float(c), val[e]);
    }
}

// ---------------- small-layer SpMM (register accumulator per lane) ----------------
// MODE 0: raw y -> other buffer   MODE 1: fused SiLU -> other buffer
// MODE 2: final, transposed (B, H3) write to outp
template <int MODE, bool IN_A>
__global__ __launch_bounds__(BT) void k_spmmS(const float* __restrict__ bias,
                                              float* __restrict__ outp) {
    const float* __restrict__ in = IN_A ? g_bufA : g_bufB;
    float* __restrict__ outbuf   = IN_A ? g_bufB : g_bufA;
    int r = blockIdx.x;
    int o = blockIdx.y * BT + threadIdx.x;
    float acc = bias[r];
    int beg = g_ptrS[r];
    int end = g_ptrS[r + 1];
#pragma unroll 4
    for (int e = beg; e < end; e++) {
        float2 E = g_entS[e];
        int c = __float_as_int(E.x);
        acc += E.y * in[c * BATCH + o];
    }
    if (MODE == 0)      outbuf[r * BATCH + o] = acc;
    else if (MODE == 1) outbuf[r * BATCH + o] = acc / (1.f + expf(-acc));
    else                outp[o * H3 + r] = acc;
}

// ---------------- host orchestration ----------------
static inline int cdiv(int a, int b) { return (a + b - 1) / b; }

static void build_small(const int* idx, const float* val, int nnz, int out_d) {
    k_zeroS<<<cdiv(out_d, 256), 256>>>(out_d);
    k_histS<<<cdiv(nnz, 256), 256>>>(idx, nnz);
    k_scanS<<<1, 1024>>>(out_d);
    k_scatterS<<<cdiv(nnz, 256), 256>>>(idx, val, nnz);
}

extern "C" void kernel_launch(void* const* d_in, const int* in_sizes, int n_in,
                              void* d_out, int out_size) {
    (void)n_in; (void)out_size;
    const float* x    = (const float*)d_in[0];
    const int*   idx1 = (const int*)d_in[1];
    const float* val1 = (const float*)d_in[2];
    const float* b1   = (const float*)d_in[3];
    const int*   idx2 = (const int*)d_in[4];
    const float* val2 = (const float*)d_in[5];
    const float* b2   = (const float*)d_in[6];
    const int*   idx3 = (const int*)d_in[7];
    const float* val3 = (const float*)d_in[8];
    const float* b3   = (const float*)d_in[9];
    const int*   idx4 = (const int*)d_in[10];
    const float* val4 = (const float*)d_in[11];
    const float* b4   = (const float*)d_in[12];
    const int*   idx5 = (const int*)d_in[13];
    const float* val5 = (const float*)d_in[14];
    const float* b5   = (const float*)d_in[15];
    const float* g1   = (const float*)d_in[16];
    const float* be1  = (const float*)d_in[17];
    const float* g2   = (const float*)d_in[18];
    const float* be2  = (const float*)d_in[19];
    const float* g3   = (const float*)d_in[20];
    const float* be3  = (const float*)d_in[21];
    float* outp = (float*)d_out;

    int nnz1 = in_sizes[2];
    int nnz2 = in_sizes[5];
    int nnz3 = in_sizes[8];
    int nnz4 = in_sizes[11];
    int nnz5 = in_sizes[14];

    // x -> xT
    k_transpose<<<dim3(D_IN / 32, BATCH / 32), dim3(32, 8)>>>(x);

    // ---- layer 1: CSC build ----
    k_zero1<<<cdiv(NB1, 256), 256>>>();
    k_hist1<<<cdiv(nnz1, 256), 256>>>(idx1, nnz1);
    k_scan1<<<NSCAN_BLK, SCAN_B>>>();
    k_scan2<<<1, 1024>>>();
    k_scan3<<<NSCAN_BLK, SCAN_B>>>();
    k_scatter1<<<cdiv(nnz1, 256), 256>>>(idx1, val1, nnz1);

    // ---- layer 1: SpMM + reduce + BN/SiLU ----
    // bucket fastest -> blocks sharing a chunk's xT slab are co-resident (L2 reuse)
    k_spmm1<<<dim3(NBUCK, BTILES, C1), BT>>>();
    k_reduce1<<<dim3(H1, BTILES), BT>>>(b1);           // -> bufA = y1
    k_bn_silu<true><<<H1, 256>>>(g1, be1);             // bufA -> bufB = h1

    // ---- layer 2 (600 -> 600, SiLU fused, no BN) ----
    build_small(idx2, val2, nnz2, H1);
    k_spmmS<1, false><<<dim3(H1, BTILES), BT>>>(b2, nullptr);   // bufB -> bufA = h2

    // ---- layer 3 (600 -> 300) + BN/SiLU ----
    build_small(idx3, val3, nnz3, H2);
    k_spmmS<0, true><<<dim3(H2, BTILES), BT>>>(b3, nullptr);    // bufA -> bufB = y3
    k_bn_silu<false><<<H2, 256>>>(g2, be2);                     // bufB -> bufA = h3

    // ---- layer 4 (300 -> 200) + BN/SiLU ----
    build_small(idx4, val4, nnz4, H3);
    k_spmmS<0, true><<<dim3(H3, BTILES), BT>>>(b4, nullptr);    // bufA -> bufB = y4
    k_bn_silu<false><<<H3, 256>>>(g3, be3);                     // bufB -> bufA = h4

    // ---- layer 5 (200 -> 200, final, transposed (B, H3) output) ----
    build_small(idx5, val5, nnz5, H3);
    k_spmmS<2, true><<<dim3(H3, BTILES), BT>>>(b5, outp);
}

// round 10
// speedup vs baseline: 2.7714x; 2.5537x over previous
#include <cuda_runtime.h>
#include <math.h>

// ---------------- problem constants ----------------
#define D_IN   120000
#define BATCH  512
#define H1     600
#define H2     300
#define H3     200

// ---------------- L1 CSC-spmm config ----------------
#define RB      24            // rows per bucket (24*128 float2 = 24576 B smem -> 8 blocks/SM)
#define NBUCK   25            // 25*24 = 600 exactly
#define BTILES  2             // 2 x 256 batch lanes (128 threads x float2)
#define C1      20            // chunks: 20*6000 = 120000 exactly
#define DC      6000
#define EB      6             // entry batch (MLP depth; keeps regs < 64)
#define NB1     (NBUCK * D_IN)          // 3,000,000 bins
#define SCAN_T  1024
#define COARSE  4
#define BIN_PER_BLK (SCAN_T * COARSE)   // 4096
#define NSCAN_BLK ((NB1 + BIN_PER_BLK - 1) / BIN_PER_BLK)   // 733

#define MAX_NNZ1 7200000
#define MAX_NNZS 36000

// ---------------- device scratch (static) ----------------
__device__ float  g_xT[(size_t)D_IN * BATCH];        // 245.8 MB transposed input
__device__ float2 g_ent1[MAX_NNZ1];                  // (key=(col<<6|row_local), val)
__device__ int    g_ptr1[NB1 + 1];
__device__ int    g_cur1[NB1];                       // histogram, then scatter cursor
__device__ int    g_bsum[1024];
__device__ int    g_bsumex[1024];
__device__ float  g_part1[(size_t)C1 * H1 * BATCH];  // 24.6 MB partials
__device__ float  g_bufA[H1 * BATCH];
__device__ float  g_bufB[H1 * BATCH];
__device__ float2 g_entS[MAX_NNZS];
__device__ int    g_ptrS[H1 + 1];
__device__ int    g_curS[H1];

// ---------------- transpose x (B x D) -> xT (D x B) ----------------
__global__ void k_transpose(const float* __restrict__ x) {
    __shared__ float tile[32][33];
    int d0 = blockIdx.x * 32;
    int b0 = blockIdx.y * 32;
    int tx = threadIdx.x, ty = threadIdx.y;      // block (32, 8)
#pragma unroll
    for (int j = 0; j < 32; j += 8)
        tile[ty + j][tx] = x[(size_t)(b0 + ty + j) * D_IN + d0 + tx];
    __syncthreads();
#pragma unroll
    for (int j = 0; j < 32; j += 8)
        g_xT[(size_t)(d0 + ty + j) * BATCH + b0 + tx] = tile[tx][ty + j];
}

// ---------------- zero kernels ----------------
__global__ void k_zero1() {
    int i = blockIdx.x * blockDim.x + threadIdx.x;
    if (i < NB1) g_cur1[i] = 0;
}
__global__ void k_zeroS(int n) {
    int i = blockIdx.x * blockDim.x + threadIdx.x;
    if (i < n) g_curS[i] = 0;
}

// ---------------- L1 build: histogram / coarse 3-phase scan / scatter ----------------
__global__ void k_hist1(const int* __restrict__ idx, int nnz) {
    int e = blockIdx.x * blockDim.x + threadIdx.x;
    if (e < nnz) {
        int r = idx[e];
        int c = idx[nnz + e];
        atomicAdd(&g_cur1[(r / RB) * D_IN + c], 1);
    }
}

__global__ void k_scan1() {  // per-block sum of 4096 bins
    __shared__ int s[SCAN_T];
    int base = blockIdx.x * BIN_PER_BLK + threadIdx.x * COARSE;
    int v = 0;
#pragma unroll
    for (int k = 0; k < COARSE; k++)
        if (base + k < NB1) v += g_cur1[base + k];
    s[threadIdx.x] = v;
    __syncthreads();
    for (int o = SCAN_T / 2; o > 0; o >>= 1) {
        if (threadIdx.x < o) s[threadIdx.x] += s[threadIdx.x + o];
        __syncthreads();
    }
    if (threadIdx.x == 0) g_bsum[blockIdx.x] = s[0];
}

__global__ void k_scan2() {  // single block: exclusive scan of block sums (733 <= 1024)
    __shared__ int s[1024];
    int t = threadIdx.x;
    int v = (t < NSCAN_BLK) ? g_bsum[t] : 0;
    s[t] = v;
    __syncthreads();
    for (int o = 1; o < 1024; o <<= 1) {
        int a = (t >= o) ? s[t - o] : 0;
        __syncthreads();
        s[t] += a;
        __syncthreads();
    }
    if (t < NSCAN_BLK) g_bsumex[t] = s[t] - v;
}

__global__ void k_scan3() {  // final scan with 4-way coarsening; writes ptr + cursor
    __shared__ int s[SCAN_T];
    int t = threadIdx.x;
    int base = blockIdx.x * BIN_PER_BLK + t * COARSE;
    int c[COARSE];
    int tot = 0;
#pragma unroll
    for (int k = 0; k < COARSE; k++) {
        c[k] = (base + k < NB1) ? g_cur1[base + k] : 0;
        tot += c[k];
    }
    s[t] = tot;
    __syncthreads();
    for (int o = 1; o < SCAN_T; o <<= 1) {
        int a = (t >= o) ? s[t - o] : 0;
        __syncthreads();
        s[t] += a;
        __syncthreads();
    }
    int excl = s[t] - tot + g_bsumex[blockIdx.x];
#pragma unroll
    for (int k = 0; k < COARSE; k++) {
        if (base + k < NB1) {
            g_ptr1[base + k] = excl;
            g_cur1[base + k] = excl;
            excl += c[k];
        }
    }
    if (blockIdx.x == NSCAN_BLK - 1 && t == SCAN_T - 1)
        g_ptr1[NB1] = excl;
}

__global__ void k_scatter1(const int* __restrict__ idx, const float* __restrict__ val, int nnz) {
    int e = blockIdx.x * blockDim.x + threadIdx.x;
    if (e < nnz) {
        int r = idx[e];
        int c = idx[nnz + e];
        int bk = r / RB;
        int pos = atomicAdd(&g_cur1[bk * D_IN + c], 1);
        g_ent1[pos] = make_float2(__int_as_float((c << 6) | (r - bk * RB)), val[e]);
    }
}

// ---------------- L1 SpMM: entry-centric stream, double-buffered loads ----------------
// Each thread owns 2 batch lanes (float2). Entry + x loads batched (MLP ~ EB..2*EB);
// next entry batch is loaded BEFORE the RMW stall. Thread-private smem RMW: no atomics.
__global__ __launch_bounds__(128, 8) void k_spmm1() {
    __shared__ float2 acc2[RB * 128];   // 24576 B
    int bucket = blockIdx.x;     // 0..24
    int bt     = blockIdx.y;     // 0..1
    int chunk  = blockIdx.z;     // 0..19
    int tid    = threadIdx.x;

#pragma unroll
    for (int i = 0; i < RB; i++) acc2[i * 128 + tid] = make_float2(0.f, 0.f);

    int c0 = chunk * DC;
    int beg = g_ptr1[bucket * D_IN + c0];
    int end = g_ptr1[bucket * D_IN + c0 + DC];
    int lo  = bt * 128 + tid;                          // float2 lane index (0..255)
    const float2* __restrict__ x2  = ((const float2*)g_xT) + lo;
    const float2* __restrict__ ent = g_ent1;

    int e = beg;
    float2 E[EB];
    bool have = (e + EB <= end);
    if (have) {
#pragma unroll
        for (int k = 0; k < EB; k++) E[k] = ent[e + k];
    }
    while (have) {
        // x gathers for current batch (dep on E)
        float2 X[EB];
#pragma unroll
        for (int k = 0; k < EB; k++) {
            int key = __float_as_int(E[k].x);
            X[k] = x2[(size_t)(key >> 6) * (BATCH / 2)];
        }
        // prefetch next entry batch before the RMW stall
        bool more = (e + 2 * EB <= end);
        float2 E2[EB];
        if (more) {
#pragma unroll
            for (int k = 0; k < EB; k++) E2[k] = ent[e + EB + k];
        }
        // serial RMW (per-thread same-address smem ordering is guaranteed)
#pragma unroll
        for (int k = 0; k < EB; k++) {
            int r = __float_as_int(E[k].x) & 63;
            float2 a = acc2[r * 128 + tid];
            a.x += E[k].y * X[k].x;
            a.y += E[k].y * X[k].y;
            acc2[r * 128 + tid] = a;
        }
        e += EB;
        if (more) {
#pragma unroll
            for (int k = 0; k < EB; k++) E[k] = E2[k];
        }
        have = more;
    }
    // scalar tail
    for (; e < end; e++) {
        float2 Et = ent[e];
        int key = __float_as_int(Et.x);
        float2 xv = x2[(size_t)(key >> 6) * (BATCH / 2)];
        int r = key & 63;
        float2 a = acc2[r * 128 + tid];
        a.x += Et.y * xv.x;
        a.y += Et.y * xv.y;
        acc2[r * 128 + tid] = a;
    }

    // non-atomic partial writes
    float2* part2 = (float2*)g_part1;
#pragma unroll
    for (int i = 0; i < RB; i++) {
        int rg = bucket * RB + i;    // < 600 always
        part2[(size_t)(chunk * H1 + rg) * (BATCH / 2) + lo] = acc2[i * 128 + tid];
    }
}

__global__ void k_reduce1(const float* __restrict__ bias) {
    int r = blockIdx.x;
    int o = blockIdx.y * 128 + threadIdx.x;    // float2 lane
    float b = bias[r];
    float2 s = make_float2(b, b);
    const float2* part2 = (const float2*)g_part1;
#pragma unroll
    for (int k = 0; k < C1; k++) {
        float2 p = part2[(size_t)(k * H1 + r) * (BATCH / 2) + o];
        s.x += p.x; s.y += p.y;
    }
    ((float2*)g_bufA)[r * (BATCH / 2) + o] = s;
}

// ---------------- BatchNorm (training mode, biased var) + SiLU ----------------
template <bool A2B>
__global__ void k_bn_silu(const float* __restrict__ g, const float* __restrict__ be) {
    const float* __restrict__ in = A2B ? g_bufA : g_bufB;
    float* __restrict__ out      = A2B ? g_bufB : g_bufA;
    __shared__ float sS[8], sQ[8];
    int r = blockIdx.x, tid = threadIdx.x;   // 256 threads
    float v0 = in[r * BATCH + tid];
    float v1 = in[r * BATCH + 256 + tid];
    float s = v0 + v1;
    float q = v0 * v0 + v1 * v1;
#pragma unroll
    for (int o = 16; o > 0; o >>= 1) {
        s += __shfl_down_sync(0xffffffffu, s, o);
        q += __shfl_down_sync(0xffffffffu, q, o);
    }
    if ((tid & 31) == 0) { sS[tid >> 5] = s; sQ[tid >> 5] = q; }
    __syncthreads();
    if (tid < 8) {
        s = sS[tid]; q = sQ[tid];
#pragma unroll
        for (int o = 4; o > 0; o >>= 1) {
            s += __shfl_down_sync(0xffu, s, o);
            q += __shfl_down_sync(0xffu, q, o);
        }
        if (tid == 0) { sS[0] = s; sQ[0] = q; }
    }
    __syncthreads();
    float mean = sS[0] * (1.f / BATCH);
    float var  = sQ[0] * (1.f / BATCH) - mean * mean;
    float sc = rsqrtf(var + 1e-5f) * g[r];
    float sh = be[r];
    float z0 = (v0 - mean) * sc + sh;
    float z1 = (v1 - mean) * sc + sh;
    out[r * BATCH + tid]       = z0 / (1.f + expf(-z0));
    out[r * BATCH + 256 + tid] = z1 / (1.f + expf(-z1));
}

// ---------------- small-layer CSR build ----------------
__global__ void k_histS(const int* __restrict__ idx, int nnz) {
    int e = blockIdx.x * blockDim.x + threadIdx.x;
    if (e < nnz) atomicAdd(&g_curS[idx[e]], 1);
}

__global__ void k_scanS(int n) {   // single block, n <= 1024
    __shared__ int s[1024];
    int t = threadIdx.x;
    int v = (t < n) ? g_curS[t] : 0;
    s[t] = v;
    __syncthreads();
    for (int o = 1; o < 1024; o <<= 1) {
        int a = (t >= o) ? s[t - o] : 0;
        __syncthreads();
        s[t] += a;
        __syncthreads();
    }
    if (t < n) { int p = s[t] - v; g_ptrS[t] = p; g_curS[t] = p; }
    if (t == 1023) g_ptrS[n] = s[1023];
}

__global__ void k_scatterS(const int* __restrict__ idx, const float* __restrict__ val, int nnz) {
    int e = blockIdx.x * blockDim.x + threadIdx.x;
    if (e < nnz) {
        int r = idx[e];
        int c = idx[nnz + e];
        int pos = atomicAdd(&g_curS[r], 1);
        g_entS[pos] = make_float2(__int_as_float(c), val[e]);
    }
}

// ---------------- small-layer SpMM ----------------
// MODE 0: raw y -> other buffer   MODE 1: fused SiLU -> other buffer
// MODE 2: final, transposed (B, H3) write to outp
template <int MODE, bool IN_A>
__global__ __launch_bounds__(128) void k_spmmS(const float* __restrict__ bias,
                                               float* __restrict__ outp) {
    const float* __restrict__ in = IN_A ? g_bufA : g_bufB;
    float* __restrict__ outbuf   = IN_A ? g_bufB : g_bufA;
    int r = blockIdx.x;
    int o = blockIdx.y * 128 + threadIdx.x;
    float acc = bias[r];
    int beg = g_ptrS[r];
    int end = g_ptrS[r + 1];
#pragma unroll 4
    for (int e = beg; e < end; e++) {
        float2 E = g_entS[e];
        int c = __float_as_int(E.x);
        acc += E.y * in[c * BATCH + o];
    }
    if (MODE == 0)      outbuf[r * BATCH + o] = acc;
    else if (MODE == 1) outbuf[r * BATCH + o] = acc / (1.f + expf(-acc));
    else                outp[o * H3 + r] = acc;
}

// ---------------- host orchestration ----------------
static inline int cdiv(int a, int b) { return (a + b - 1) / b; }

static void build_small(const int* idx, const float* val, int nnz, int out_d) {
    k_zeroS<<<cdiv(out_d, 256), 256>>>(out_d);
    k_histS<<<cdiv(nnz, 256), 256>>>(idx, nnz);
    k_scanS<<<1, 1024>>>(out_d);
    k_scatterS<<<cdiv(nnz, 256), 256>>>(idx, val, nnz);
}

extern "C" void kernel_launch(void* const* d_in, const int* in_sizes, int n_in,
                              void* d_out, int out_size) {
    (void)n_in; (void)out_size;
    const float* x    = (const float*)d_in[0];
    const int*   idx1 = (const int*)d_in[1];
    const float* val1 = (const float*)d_in[2];
    const float* b1   = (const float*)d_in[3];
    const int*   idx2 = (const int*)d_in[4];
    const float* val2 = (const float*)d_in[5];
    const float* b2   = (const float*)d_in[6];
    const int*   idx3 = (const int*)d_in[7];
    const float* val3 = (const float*)d_in[8];
    const float* b3   = (const float*)d_in[9];
    const int*   idx4 = (const int*)d_in[10];
    const float* val4 = (const float*)d_in[11];
    const float* b4   = (const float*)d_in[12];
    const int*   idx5 = (const int*)d_in[13];
    const float* val5 = (const float*)d_in[14];
    const float* b5   = (const float*)d_in[15];
    const float* g1   = (const float*)d_in[16];
    const float* be1  = (const float*)d_in[17];
    const float* g2   = (const float*)d_in[18];
    const float* be2  = (const float*)d_in[19];
    const float* g3   = (const float*)d_in[20];
    const float* be3  = (const float*)d_in[21];
    float* outp = (float*)d_out;

    int nnz1 = in_sizes[2];
    int nnz2 = in_sizes[5];
    int nnz3 = in_sizes[8];
    int nnz4 = in_sizes[11];
    int nnz5 = in_sizes[14];

    // x -> xT
    k_transpose<<<dim3(D_IN / 32, BATCH / 32), dim3(32, 8)>>>(x);

    // ---- layer 1: CSC build ----
    k_zero1<<<cdiv(NB1, 256), 256>>>();
    k_hist1<<<cdiv(nnz1, 256), 256>>>(idx1, nnz1);
    k_scan1<<<NSCAN_BLK, SCAN_T>>>();
    k_scan2<<<1, 1024>>>();
    k_scan3<<<NSCAN_BLK, SCAN_T>>>();
    k_scatter1<<<cdiv(nnz1, 256), 256>>>(idx1, val1, nnz1);

    // ---- layer 1: SpMM + reduce + BN/SiLU ----
    // bucket fastest: co-chunk blocks co-resident -> x slab L2 reuse
    k_spmm1<<<dim3(NBUCK, BTILES, C1), 128>>>();
    k_reduce1<<<dim3(H1, BATCH / 2 / 128), 128>>>(b1);   // -> bufA = y1
    k_bn_silu<true><<<H1, 256>>>(g1, be1);               // bufA -> bufB = h1

    // ---- layer 2 (600 -> 600, SiLU fused, no BN) ----
    build_small(idx2, val2, nnz2, H1);
    k_spmmS<1, false><<<dim3(H1, BATCH / 128), 128>>>(b2, nullptr);   // bufB -> bufA = h2

    // ---- layer 3 (600 -> 300) + BN/SiLU ----
    build_small(idx3, val3, nnz3, H2);
    k_spmmS<0, true><<<dim3(H2, BATCH / 128), 128>>>(b3, nullptr);    // bufA -> bufB = y3
    k_bn_silu<false><<<H2, 256>>>(g2, be2);                           // bufB -> bufA = h3

    // ---- layer 4 (300 -> 200) + BN/SiLU ----
    build_small(idx4, val4, nnz4, H3);
    k_spmmS<0, true><<<dim3(H3, BATCH / 128), 128>>>(b4, nullptr);    // bufA -> bufB = y4
    k_bn_silu<false><<<H3, 256>>>(g3, be3);                           // bufB -> bufA = h4

    // ---- layer 5 (200 -> 200, final, transposed (B, H3) output) ----
    build_small(idx5, val5, nnz5, H3);
    k_spmmS<2, true><<<dim3(H3, BATCH / 128), 128>>>(b5, outp);
}